// round 2
// baseline (speedup 1.0000x reference)
#include <cuda_runtime.h>

// Problem constants (fixed by setup_inputs)
#define CB 8
#define CH 96
#define CW 96
#define CC 192
#define CT (CH*CW)          // 9216
#define CM (CB*CT)          // 73728
#define L2E 1.4426950408889634f

// ---------------- scratch (static __device__; no runtime allocation) -------
__device__ float g_cw[25*CC];            // combined 5x5 dw weights, [tap][C]
__device__ float g_xs[CM*CC];            // omni-shift output
__device__ float g_k [CM*CC];
__device__ float g_v [CM*CC];            // v -> y1 -> y2 (in-place)
__device__ float g_r [CM*CC];            // sigmoid(r)
__device__ float g_sp[CB*96*CC];         // chunk summary / start-state p
__device__ float g_sq[CB*96*CC];
__device__ float g_so[CB*96*CC];         // start-state log-scale o

// ---------------- 1. combine omni-shift weights ---------------------------
__global__ void combine_cw(const float* __restrict__ alpha,
                           const float* __restrict__ w1,
                           const float* __restrict__ w3,
                           const float* __restrict__ w5) {
    int idx = blockIdx.x * blockDim.x + threadIdx.x;
    if (idx >= CC*25) return;
    int c = idx / 25, tap = idx % 25;
    int dy = tap / 5, dx = tap % 5;
    float v = alpha[3] * w5[c*25 + tap];
    if (dy == 2 && dx == 2) v += alpha[0] + alpha[1] * w1[c];
    if (dy >= 1 && dy <= 3 && dx >= 1 && dx <= 3)
        v += alpha[2] * w3[c*9 + (dy-1)*3 + (dx-1)];
    g_cw[tap*CC + c] = v;   // transposed: [tap][C] so conv can load float2 per-channel-pair
}

// ---------------- 2. depthwise 5x5 conv (zero pad) -------------------------
// block = 96 threads, each owns 2 channels (float2); grid = (H, B)
__global__ void conv5(const float* __restrict__ x) {
    int h = blockIdx.x, b = blockIdx.y;
    int c2 = threadIdx.x * 2;
    float2 wreg[25];
#pragma unroll
    for (int tap = 0; tap < 25; tap++)
        wreg[tap] = *(const float2*)&g_cw[tap*CC + c2];
    const float* xb = x    + (size_t)b*CT*CC;
    float*       ob = g_xs + (size_t)b*CT*CC;
    for (int w = 0; w < CW; w++) {
        float ax = 0.f, ay = 0.f;
#pragma unroll
        for (int dy = 0; dy < 5; dy++) {
            int hy = h + dy - 2;
            if ((unsigned)hy >= CH) continue;
            const float* rb = xb + (size_t)(hy*CW)*CC + c2;
#pragma unroll
            for (int dx = 0; dx < 5; dx++) {
                int wx = w + dx - 2;
                if ((unsigned)wx >= CW) continue;
                float2 xv = *(const float2*)&rb[(size_t)wx*CC];
                ax = fmaf(wreg[dy*5+dx].x, xv.x, ax);
                ay = fmaf(wreg[dy*5+dx].y, xv.y, ay);
            }
        }
        *(float2*)&ob[(size_t)(h*CW + w)*CC + c2] = make_float2(ax, ay);
    }
}

// ---------------- 3. SGEMM: Y = xs @ [Wk;Wv;Wr]^T (sigmoid on r) ----------
#define BM 128
#define BN 64
#define BK 16

__global__ __launch_bounds__(256) void gemm_kvr(const float* __restrict__ Wk,
                                                const float* __restrict__ Wv,
                                                const float* __restrict__ Wr) {
    __shared__ __align__(16) float As[BK][BM+4];
    __shared__ __align__(16) float Bs[BK][BN+4];
    int tid = threadIdx.x;
    int nb = blockIdx.x * BN;           // 0..512, multiple of 64
    int mb = blockIdx.y * BM;
    const float* Wsrc; float* Out; int sel;
    if (nb < CC)        { Wsrc = Wk; Out = g_k; sel = 0; }
    else if (nb < 2*CC) { Wsrc = Wv; Out = g_v; sel = 1; }
    else                { Wsrc = Wr; Out = g_r; sel = 2; }
    int nloc = nb % CC;
    int tx = tid & 15, ty = tid >> 4;
    float acc[8][4];
#pragma unroll
    for (int i = 0; i < 8; i++)
#pragma unroll
        for (int j = 0; j < 4; j++) acc[i][j] = 0.f;

    int ar = tid >> 2;                  // 0..63
    int ak = (tid & 3) * 4;             // 0,4,8,12

    for (int k0 = 0; k0 < CC; k0 += BK) {
        float4 a0 = *(const float4*)&g_xs[(size_t)(mb + ar     )*CC + k0 + ak];
        float4 a1 = *(const float4*)&g_xs[(size_t)(mb + ar + 64)*CC + k0 + ak];
        float4 bv = *(const float4*)&Wsrc[(size_t)(nloc + ar   )*CC + k0 + ak];
        __syncthreads();
        As[ak+0][ar] = a0.x; As[ak+1][ar] = a0.y; As[ak+2][ar] = a0.z; As[ak+3][ar] = a0.w;
        As[ak+0][ar+64] = a1.x; As[ak+1][ar+64] = a1.y; As[ak+2][ar+64] = a1.z; As[ak+3][ar+64] = a1.w;
        Bs[ak+0][ar] = bv.x; Bs[ak+1][ar] = bv.y; Bs[ak+2][ar] = bv.z; Bs[ak+3][ar] = bv.w;
        __syncthreads();
#pragma unroll
        for (int kk = 0; kk < BK; kk++) {
            float4 bf  = *(const float4*)&Bs[kk][tx*4];
            float4 af0 = *(const float4*)&As[kk][ty*8];
            float4 af1 = *(const float4*)&As[kk][ty*8+4];
            float aa[8] = {af0.x, af0.y, af0.z, af0.w, af1.x, af1.y, af1.z, af1.w};
            float bb[4] = {bf.x, bf.y, bf.z, bf.w};
#pragma unroll
            for (int i = 0; i < 8; i++)
#pragma unroll
                for (int j = 0; j < 4; j++)
                    acc[i][j] = fmaf(aa[i], bb[j], acc[i][j]);
        }
    }
#pragma unroll
    for (int i = 0; i < 8; i++) {
        float4 o = make_float4(acc[i][0], acc[i][1], acc[i][2], acc[i][3]);
        if (sel == 2) {
            o.x = 1.f/(1.f+__expf(-o.x)); o.y = 1.f/(1.f+__expf(-o.y));
            o.z = 1.f/(1.f+__expf(-o.z)); o.w = 1.f/(1.f+__expf(-o.w));
        }
        *(float4*)&Out[(size_t)(mb + ty*8 + i)*CC + nloc + tx*4] = o;
    }
}

// ---------------- 4. WKV chunked parallel scan -----------------------------
// chunk = 96 steps. pass1: per-chunk additive accumulation (decay folded into
// exponent). cscan: stabilized log-space combine across 96 chunks per chain.
// pass2: replay chunk from precomputed start state, emit y (in-place on v).

__global__ void wkv_pass1(const float* __restrict__ sd, int sC, int sI) {
    int ci = blockIdx.x, b = blockIdx.y, c = threadIdx.x;
    float w  = sd[c] * (1.0f/(float)CT);
    float wl = w * L2E;
    float S = 0.f, Sq = 0.f, off = -wl;
    size_t base = (size_t)b*CT*CC + c;
    int t = ci * sC;
    for (int i = 0; i < 96; i++) {
        size_t o = base + (size_t)t*CC;
        float kt = g_k[o], vt = g_v[o];
        float E = exp2f(fmaf(kt, L2E, off));   // e^{k - w*(i+1)}
        S  = fmaf(E, vt, S);
        Sq += E;
        off -= wl;
        t += sI;
    }
    int sidx = (b*96 + ci)*CC + c;
    g_sp[sidx] = S; g_sq[sidx] = Sq;           // summary at log-scale oc = 96w
}

__global__ void wkv_cscan(const float* __restrict__ sd) {
    int b = blockIdx.x, c = threadIdx.x;
    float w   = sd[c] * (1.0f/(float)CT);
    float W96 = 96.f * w;                       // per-chunk decay / summary scale
    float p = 0.f, q = 0.f, o = -1e38f;
    for (int ci = 0; ci < 96; ci++) {
        int sidx = (b*96 + ci)*CC + c;
        float Pc = g_sp[sidx], Qc = g_sq[sidx];
        g_sp[sidx] = p; g_sq[sidx] = q; g_so[sidx] = o;   // chunk-start state
        float o1 = o + W96;
        float no = fmaxf(o1, W96);
        float e1 = exp2f((o1 - no)*L2E);
        float e2 = exp2f((W96 - no)*L2E);
        p = fmaf(e1, p, e2*Pc);
        q = fmaf(e1, q, e2*Qc);
        o = no;
    }
}

__global__ void wkv_pass2(const float* __restrict__ sd, const float* __restrict__ sf,
                          int sC, int sI) {
    int ci = blockIdx.x, b = blockIdx.y, c = threadIdx.x;
    float w  = sd[c] * (1.0f/(float)CT);
    float u  = sf[c] * (1.0f/(float)CT);
    float wl = w * L2E;
    float c1 = exp2f(-(u + w)*L2E);            // E = Eu * e^{-u-w}
    int sidx = (b*96 + ci)*CC + c;
    float p = g_sp[sidx], q = g_sq[sidx], o = g_so[sidx];
    float offu;
    if (o < -1e30f) { p = 0.f; q = 0.f; offu = u*L2E; }
    else            { offu = (u - o)*L2E; }
    size_t base = (size_t)b*CT*CC + c;
    int t = ci * sC;
    for (int i = 0; i < 96; i++) {
        size_t off = base + (size_t)t*CC;
        float kt = g_k[off], vt = g_v[off];
        float Eu = exp2f(fmaf(kt, L2E, offu)); // e^{u + k - m - w*i}
        float y  = __fdividef(fmaf(Eu, vt, p), q + Eu);
        g_v[off] = y;                           // read-before-write, in-place safe
        float E = Eu * c1;                      // e^{k - m - w*(i+1)}
        p = fmaf(E, vt, p);
        q += E;
        offu -= wl;
        t += sI;
    }
}

// ---------------- 5. SGEMM: out = (sr * v) @ Wo^T (A fused on load) --------
__global__ __launch_bounds__(256) void gemm_out(const float* __restrict__ Wo,
                                                float* __restrict__ out) {
    __shared__ __align__(16) float As[BK][BM+4];
    __shared__ __align__(16) float Bs[BK][BN+4];
    int tid = threadIdx.x;
    int nb = blockIdx.x * BN;
    int mb = blockIdx.y * BM;
    int tx = tid & 15, ty = tid >> 4;
    float acc[8][4];
#pragma unroll
    for (int i = 0; i < 8; i++)
#pragma unroll
        for (int j = 0; j < 4; j++) acc[i][j] = 0.f;
    int ar = tid >> 2;
    int ak = (tid & 3) * 4;

    for (int k0 = 0; k0 < CC; k0 += BK) {
        size_t aoff0 = (size_t)(mb + ar)*CC + k0 + ak;
        size_t aoff1 = aoff0 + (size_t)64*CC;
        float4 r0 = *(const float4*)&g_r[aoff0];
        float4 v0 = *(const float4*)&g_v[aoff0];
        float4 r1 = *(const float4*)&g_r[aoff1];
        float4 v1 = *(const float4*)&g_v[aoff1];
        float4 bv = *(const float4*)&Wo[(size_t)(nb + ar)*CC + k0 + ak];
        float4 a0 = make_float4(r0.x*v0.x, r0.y*v0.y, r0.z*v0.z, r0.w*v0.w);
        float4 a1 = make_float4(r1.x*v1.x, r1.y*v1.y, r1.z*v1.z, r1.w*v1.w);
        __syncthreads();
        As[ak+0][ar] = a0.x; As[ak+1][ar] = a0.y; As[ak+2][ar] = a0.z; As[ak+3][ar] = a0.w;
        As[ak+0][ar+64] = a1.x; As[ak+1][ar+64] = a1.y; As[ak+2][ar+64] = a1.z; As[ak+3][ar+64] = a1.w;
        Bs[ak+0][ar] = bv.x; Bs[ak+1][ar] = bv.y; Bs[ak+2][ar] = bv.z; Bs[ak+3][ar] = bv.w;
        __syncthreads();
#pragma unroll
        for (int kk = 0; kk < BK; kk++) {
            float4 bf  = *(const float4*)&Bs[kk][tx*4];
            float4 af0 = *(const float4*)&As[kk][ty*8];
            float4 af1 = *(const float4*)&As[kk][ty*8+4];
            float aa[8] = {af0.x, af0.y, af0.z, af0.w, af1.x, af1.y, af1.z, af1.w};
            float bb[4] = {bf.x, bf.y, bf.z, bf.w};
#pragma unroll
            for (int i = 0; i < 8; i++)
#pragma unroll
                for (int j = 0; j < 4; j++)
                    acc[i][j] = fmaf(aa[i], bb[j], acc[i][j]);
        }
    }
#pragma unroll
    for (int i = 0; i < 8; i++) {
        float4 o = make_float4(acc[i][0], acc[i][1], acc[i][2], acc[i][3]);
        *(float4*)&out[(size_t)(mb + ty*8 + i)*CC + nb + tx*4] = o;
    }
}

// ---------------- launcher -------------------------------------------------
extern "C" void kernel_launch(void* const* d_in, const int* in_sizes, int n_in,
                              void* d_out, int out_size) {
    const float* x     = (const float*)d_in[0];
    const float* alpha = (const float*)d_in[1];
    const float* w1    = (const float*)d_in[2];
    const float* w3    = (const float*)d_in[3];
    const float* w5    = (const float*)d_in[4];
    const float* Wk    = (const float*)d_in[5];
    const float* Wv    = (const float*)d_in[6];
    const float* Wr    = (const float*)d_in[7];
    const float* Wo    = (const float*)d_in[8];
    const float* sd    = (const float*)d_in[9];
    const float* sf    = (const float*)d_in[10];
    float* out = (float*)d_out;

    combine_cw<<<(CC*25 + 255)/256, 256>>>(alpha, w1, w3, w5);
    conv5<<<dim3(CH, CB), CC/2>>>(x);
    gemm_kvr<<<dim3(3*CC/BN, CM/BM), 256>>>(Wk, Wv, Wr);

    // scan j = 0: row-major (chunk = image row h, inner over w)
    wkv_pass1<<<dim3(96, CB), CC>>>(sd, CW, 1);
    wkv_cscan<<<CB, CC>>>(sd);
    wkv_pass2<<<dim3(96, CB), CC>>>(sd, sf, CW, 1);

    // scan j = 1: column-major (chunk = image column w, inner over h)
    wkv_pass1<<<dim3(96, CB), CC>>>(sd + CC, 1, CW);
    wkv_cscan<<<CB, CC>>>(sd + CC);
    wkv_pass2<<<dim3(96, CB), CC>>>(sd + CC, sf + CC, 1, CW);

    gemm_out<<<dim3(CC/BN, CM/BM), 256>>>(Wo, out);
}

// round 6
// speedup vs baseline: 1.7725x; 1.7725x over previous
#include <cuda_runtime.h>
#include <cuda_bf16.h>
#include <cstdint>

// Problem constants (fixed by setup_inputs)
#define CB 8
#define CH 96
#define CW 96
#define CC 192
#define CT (CH*CW)          // 9216
#define CM (CB*CT)          // 73728
#define L2E 1.4426950408889634f
#define NCHUNK 192
#define CS 48               // wkv chunk size

// ---------------- scratch (static __device__; no runtime allocation) -------
__device__ __align__(16) float g_cw[25*CC];     // combined 5x5 dw weights [tap][C]
__device__ __align__(16) float g_xs[CM*CC];     // omni-shift output
__device__ __align__(16) float g_k [CM*CC];
__device__ __align__(16) float g_v [CM*CC];     // v -> y1 -> y2 (in-place)
__device__ __align__(16) float g_r [CM*CC];     // sigmoid(r)
__device__ __align__(16) float g_sp[CB*NCHUNK*CC];
__device__ __align__(16) float g_sq[CB*NCHUNK*CC];
__device__ __align__(16) float g_so[CB*NCHUNK*CC];

// ---------------- 1. combine omni-shift weights ---------------------------
__global__ void combine_cw(const float* __restrict__ alpha,
                           const float* __restrict__ w1,
                           const float* __restrict__ w3,
                           const float* __restrict__ w5) {
    int idx = blockIdx.x * blockDim.x + threadIdx.x;
    if (idx >= CC*25) return;
    int c = idx / 25, tap = idx % 25;
    int dy = tap / 5, dx = tap % 5;
    float v = alpha[3] * w5[c*25 + tap];
    if (dy == 2 && dx == 2) v += alpha[0] + alpha[1] * w1[c];
    if (dy >= 1 && dy <= 3 && dx >= 1 && dx <= 3)
        v += alpha[2] * w3[c*9 + (dy-1)*3 + (dx-1)];
    g_cw[tap*CC + c] = v;
}

// ---------------- 2. depthwise 5x5 conv: thread-per-channel sliding window -
__global__ __launch_bounds__(CC) void conv5(const float* __restrict__ x) {
    int h = blockIdx.x, b = blockIdx.y, c = threadIdx.x;
    float wr[25];
#pragma unroll
    for (int t = 0; t < 25; t++) wr[t] = g_cw[t*CC + c];
    bool rv[5];
#pragma unroll
    for (int dy = 0; dy < 5; dy++) rv[dy] = (unsigned)(h - 2 + dy) < CH;
    const float* xb = x    + (size_t)b*CT*CC + c;
    float*       ob = g_xs + (size_t)b*CT*CC + c;
    float win[5][5];
#pragma unroll
    for (int dy = 0; dy < 5; dy++) {
        int hy = h - 2 + dy;
        win[dy][0] = 0.f; win[dy][1] = 0.f;
        win[dy][2] = rv[dy] ? xb[(size_t)(hy*CW + 0)*CC] : 0.f;
        win[dy][3] = rv[dy] ? xb[(size_t)(hy*CW + 1)*CC] : 0.f;
        win[dy][4] = 0.f;
    }
#pragma unroll 4
    for (int w = 0; w < CW; w++) {
        int wx = w + 2;
        bool cv = wx < CW;
#pragma unroll
        for (int dy = 0; dy < 5; dy++)
            win[dy][4] = (rv[dy] && cv) ? xb[(size_t)((h-2+dy)*CW + wx)*CC] : 0.f;
        float acc = 0.f;
#pragma unroll
        for (int dy = 0; dy < 5; dy++)
#pragma unroll
            for (int j = 0; j < 5; j++)
                acc = fmaf(win[dy][j], wr[dy*5+j], acc);
        ob[(size_t)(h*CW + w)*CC] = acc;
#pragma unroll
        for (int dy = 0; dy < 5; dy++)
#pragma unroll
            for (int j = 0; j < 4; j++)
                win[dy][j] = win[dy][j+1];
    }
}

// ================= HMMA bf16 GEMM (mma.sync, sm_80 PTX — valid at sm_100) ==
// C[m,n] = sum_k A[m,k] * W[n,k].  bf16 2-term split: Ah*Bh + Ah*Bl + Al*Bh.
// CTA tile 128x96, warp tile 32x48, BK=32, fp32->bf16 split on load.

#define GSTRIDE 40   // smem row stride in bf16 elements (80 bytes)

__device__ __forceinline__ void split2(float a, float b, uint32_t& hi, uint32_t& lo) {
    __nv_bfloat16 ha = __float2bfloat16(a), hb = __float2bfloat16(b);
    float ra = a - __bfloat162float(ha), rb = b - __bfloat162float(hb);
    __nv_bfloat16 la = __float2bfloat16(ra), lb = __float2bfloat16(rb);
    hi = ((uint32_t)__bfloat16_as_ushort(hb) << 16) | (uint32_t)__bfloat16_as_ushort(ha);
    lo = ((uint32_t)__bfloat16_as_ushort(lb) << 16) | (uint32_t)__bfloat16_as_ushort(la);
}
__device__ __forceinline__ uint32_t smem_u32(const void* p) {
    uint32_t a;
    asm("{ .reg .u64 t; cvta.to.shared.u64 t, %1; cvt.u32.u64 %0, t; }" : "=r"(a) : "l"(p));
    return a;
}
__device__ __forceinline__ void ldsm4(uint32_t* r, uint32_t addr) {
    asm volatile("ldmatrix.sync.aligned.m8n8.x4.shared.b16 {%0,%1,%2,%3}, [%4];"
        : "=r"(r[0]), "=r"(r[1]), "=r"(r[2]), "=r"(r[3]) : "r"(addr));
}
__device__ __forceinline__ void mma_bf16(float* c, const uint32_t* a, uint32_t b0, uint32_t b1) {
    asm volatile("mma.sync.aligned.m16n8k16.row.col.f32.bf16.bf16.f32 "
        "{%0,%1,%2,%3}, {%4,%5,%6,%7}, {%8,%9}, {%0,%1,%2,%3};"
        : "+f"(c[0]), "+f"(c[1]), "+f"(c[2]), "+f"(c[3])
        : "r"(a[0]), "r"(a[1]), "r"(a[2]), "r"(a[3]), "r"(b0), "r"(b1));
}

struct GemmSmem {
    uint16_t Ah[128*GSTRIDE];
    uint16_t Al[128*GSTRIDE];
    uint16_t Bh[96*GSTRIDE];
    uint16_t Bl[96*GSTRIDE];
};

// Shared GEMM core. is_out=false: A = g_xs; true: A = g_r*g_v elementwise.
__device__ __forceinline__ void gemm_core(bool is_out, const float* __restrict__ Wsrc,
                                          float* __restrict__ Out, int nloc, int mb,
                                          bool dosig, GemmSmem& S) {
    int tid = threadIdx.x, lane = tid & 31, wid = tid >> 5;
    int warp_m = (wid & 3) * 32, warp_n = (wid >> 2) * 48;

    float acc[2][6][4];
#pragma unroll
    for (int i = 0; i < 2; i++)
#pragma unroll
        for (int j = 0; j < 6; j++)
#pragma unroll
            for (int q = 0; q < 4; q++) acc[i][j][q] = 0.f;

    int aRow[4], aKq[4], bRow[3], bKq[3];
#pragma unroll
    for (int p = 0; p < 4; p++) { int idx = tid + 256*p; aRow[p] = idx >> 3; aKq[p] = idx & 7; }
#pragma unroll
    for (int p = 0; p < 3; p++) { int idx = tid + 256*p; bRow[p] = idx >> 3; bKq[p] = idx & 7; }

    float4 pa[4], pb[3];
#pragma unroll
    for (int p = 0; p < 4; p++) {
        size_t off = (size_t)(mb + aRow[p])*CC + aKq[p]*4;
        if (!is_out) pa[p] = *(const float4*)&g_xs[off];
        else {
            float4 r = *(const float4*)&g_r[off];
            float4 v = *(const float4*)&g_v[off];
            pa[p] = make_float4(r.x*v.x, r.y*v.y, r.z*v.z, r.w*v.w);
        }
    }
#pragma unroll
    for (int p = 0; p < 3; p++)
        pb[p] = *(const float4*)&Wsrc[(size_t)(nloc + bRow[p])*CC + bKq[p]*4];

    uint32_t ah_b = smem_u32(S.Ah), al_b = smem_u32(S.Al);
    uint32_t bh_b = smem_u32(S.Bh), bl_b = smem_u32(S.Bl);

#pragma unroll 1
    for (int st = 0; st < 6; st++) {
        __syncthreads();
#pragma unroll
        for (int p = 0; p < 4; p++) {
            uint32_t h0, l0, h1, l1;
            split2(pa[p].x, pa[p].y, h0, l0);
            split2(pa[p].z, pa[p].w, h1, l1);
            int bo = aRow[p]*(GSTRIDE*2) + aKq[p]*8;
            *(uint2*)((char*)S.Ah + bo) = make_uint2(h0, h1);
            *(uint2*)((char*)S.Al + bo) = make_uint2(l0, l1);
        }
#pragma unroll
        for (int p = 0; p < 3; p++) {
            uint32_t h0, l0, h1, l1;
            split2(pb[p].x, pb[p].y, h0, l0);
            split2(pb[p].z, pb[p].w, h1, l1);
            int bo = bRow[p]*(GSTRIDE*2) + bKq[p]*8;
            *(uint2*)((char*)S.Bh + bo) = make_uint2(h0, h1);
            *(uint2*)((char*)S.Bl + bo) = make_uint2(l0, l1);
        }
        __syncthreads();
        if (st < 5) {
            int k0 = (st + 1) * 32;
#pragma unroll
            for (int p = 0; p < 4; p++) {
                size_t off = (size_t)(mb + aRow[p])*CC + k0 + aKq[p]*4;
                if (!is_out) pa[p] = *(const float4*)&g_xs[off];
                else {
                    float4 r = *(const float4*)&g_r[off];
                    float4 v = *(const float4*)&g_v[off];
                    pa[p] = make_float4(r.x*v.x, r.y*v.y, r.z*v.z, r.w*v.w);
                }
            }
#pragma unroll
            for (int p = 0; p < 3; p++)
                pb[p] = *(const float4*)&Wsrc[(size_t)(nloc + bRow[p])*CC + k0 + bKq[p]*4];
        }
#pragma unroll 1
        for (int ks = 0; ks < 2; ks++) {
            int arow = warp_m + (lane & 15);
            int acol = ks*16 + (lane >> 4)*8;
            uint32_t ahf[2][4], alf[2][4];
#pragma unroll
            for (int mt = 0; mt < 2; mt++) {
                uint32_t bo = (uint32_t)((arow + mt*16)*(GSTRIDE*2) + acol*2);
                ldsm4(ahf[mt], ah_b + bo);
                ldsm4(alf[mt], al_b + bo);
            }
            int brow = warp_n + (lane & 7) + ((lane >> 4) << 3);
            int bcol = ks*16 + (((lane >> 3) & 1) << 3);
#pragma unroll
            for (int np = 0; np < 3; np++) {
                uint32_t bhf[4], blf[4];
                uint32_t bo = (uint32_t)((brow + np*16)*(GSTRIDE*2) + bcol*2);
                ldsm4(bhf, bh_b + bo);
                ldsm4(blf, bl_b + bo);
#pragma unroll
                for (int half = 0; half < 2; half++) {
                    int nt = np*2 + half;
#pragma unroll
                    for (int mt = 0; mt < 2; mt++) {
                        mma_bf16(acc[mt][nt], ahf[mt], bhf[half*2], bhf[half*2+1]);
                        mma_bf16(acc[mt][nt], ahf[mt], blf[half*2], blf[half*2+1]);
                        mma_bf16(acc[mt][nt], alf[mt], bhf[half*2], bhf[half*2+1]);
                    }
                }
            }
        }
    }

    int g = lane >> 2, tig = lane & 3;
#pragma unroll
    for (int mt = 0; mt < 2; mt++) {
#pragma unroll
        for (int nt = 0; nt < 6; nt++) {
            int m0 = mb + warp_m + mt*16 + g;
            int col = nloc + warp_n + nt*8 + tig*2;
            float2 v0 = make_float2(acc[mt][nt][0], acc[mt][nt][1]);
            float2 v1 = make_float2(acc[mt][nt][2], acc[mt][nt][3]);
            if (dosig) {
                v0.x = 1.f/(1.f+__expf(-v0.x)); v0.y = 1.f/(1.f+__expf(-v0.y));
                v1.x = 1.f/(1.f+__expf(-v1.x)); v1.y = 1.f/(1.f+__expf(-v1.y));
            }
            *(float2*)&Out[(size_t)m0*CC + col]     = v0;
            *(float2*)&Out[(size_t)(m0+8)*CC + col] = v1;
        }
    }
}

__global__ __launch_bounds__(256)
void gemm_kvr_h(const float* __restrict__ Wk, const float* __restrict__ Wv,
                const float* __restrict__ Wr) {
    __shared__ __align__(16) GemmSmem S;
    int nb = blockIdx.x * 96;
    int sel = nb / CC, nloc = nb % CC;
    const float* Wsrc = (sel == 0) ? Wk : (sel == 1) ? Wv : Wr;
    float* Out        = (sel == 0) ? g_k : (sel == 1) ? g_v : g_r;
    gemm_core(false, Wsrc, Out, nloc, blockIdx.y * 128, sel == 2, S);
}

__global__ __launch_bounds__(256)
void gemm_out_h(const float* __restrict__ Wo, float* __restrict__ outp) {
    __shared__ __align__(16) GemmSmem S;
    gemm_core(true, Wo, outp, blockIdx.x * 96, blockIdx.y * 128, false, S);
}

// ---------------- 4. WKV chunked parallel scan (chunk = 48) ----------------
// j=0: chunk ci covers linear t = ci*48 + s (stride 1)
// j=1: chunk ci covers column w = ci>>1, rows h = (ci&1)*48 + s (stride CW)

__device__ __forceinline__ void chunk_map(int ci, int j, int& t0, int& stp) {
    if (j == 0) { t0 = ci * CS; stp = 1; }
    else        { t0 = ((ci & 1) * CS) * CW + (ci >> 1); stp = CW; }
}

__global__ void wkv_pass1(const float* __restrict__ sd, int j) {
    int ci = blockIdx.x, b = blockIdx.y, c = threadIdx.x;
    float w  = sd[c] * (1.0f/(float)CT);
    float wl = w * L2E;
    float S = 0.f, Sq = 0.f, off = -wl;
    size_t base = (size_t)b*CT*CC + c;
    int t0, stp; chunk_map(ci, j, t0, stp);
    size_t o = base + (size_t)t0*CC;
    size_t ostep = (size_t)stp*CC;
    float kc = g_k[o], vc = g_v[o];
#pragma unroll 4
    for (int i = 0; i < CS; i++) {
        o += ostep;
        float kn = 0.f, vn = 0.f;
        if (i < CS-1) { kn = g_k[o]; vn = g_v[o]; }
        float E = exp2f(fmaf(kc, L2E, off));
        S  = fmaf(E, vc, S);
        Sq += E;
        off -= wl;
        kc = kn; vc = vn;
    }
    int sidx = (b*NCHUNK + ci)*CC + c;
    g_sp[sidx] = S; g_sq[sidx] = Sq;
}

__global__ void wkv_cscan(const float* __restrict__ sd) {
    int b = blockIdx.x, c = threadIdx.x;
    float w  = sd[c] * (1.0f/(float)CT);
    float Wc = (float)CS * w;
    float p = 0.f, q = 0.f, o = -1e38f;
    for (int ci = 0; ci < NCHUNK; ci++) {
        int sidx = (b*NCHUNK + ci)*CC + c;
        float Pc = g_sp[sidx], Qc = g_sq[sidx];
        g_sp[sidx] = p; g_sq[sidx] = q; g_so[sidx] = o;
        float o1 = o + Wc;
        float no = fmaxf(o1, Wc);
        float e1 = exp2f((o1 - no)*L2E);
        float e2 = exp2f((Wc - no)*L2E);
        p = fmaf(e1, p, e2*Pc);
        q = fmaf(e1, q, e2*Qc);
        o = no;
    }
}

__global__ void wkv_pass2(const float* __restrict__ sd, const float* __restrict__ sf,
                          int j) {
    int ci = blockIdx.x, b = blockIdx.y, c = threadIdx.x;
    float w  = sd[c] * (1.0f/(float)CT);
    float u  = sf[c] * (1.0f/(float)CT);
    float wl = w * L2E;
    float c1 = exp2f(-(u + w)*L2E);
    int sidx = (b*NCHUNK + ci)*CC + c;
    float p = g_sp[sidx], q = g_sq[sidx], o = g_so[sidx];
    float offu;
    if (o < -1e30f) { p = 0.f; q = 0.f; offu = u*L2E; }
    else            { offu = (u - o)*L2E; }
    size_t base = (size_t)b*CT*CC + c;
    int t0, stp; chunk_map(ci, j, t0, stp);
    size_t oc = base + (size_t)t0*CC;
    size_t ostep = (size_t)stp*CC;
    float kc = g_k[oc], vc = g_v[oc];
#pragma unroll 4
    for (int i = 0; i < CS; i++) {
        size_t on = oc + ostep;
        float kn = 0.f, vn = 0.f;
        if (i < CS-1) { kn = g_k[on]; vn = g_v[on]; }
        float Eu = exp2f(fmaf(kc, L2E, offu));
        float y  = __fdividef(fmaf(Eu, vc, p), q + Eu);
        g_v[oc] = y;
        float E = Eu * c1;
        p = fmaf(E, vc, p);
        q += E;
        offu -= wl;
        oc = on; kc = kn; vc = vn;
    }
}

// ---------------- launcher -------------------------------------------------
extern "C" void kernel_launch(void* const* d_in, const int* in_sizes, int n_in,
                              void* d_out, int out_size) {
    const float* x     = (const float*)d_in[0];
    const float* alpha = (const float*)d_in[1];
    const float* w1    = (const float*)d_in[2];
    const float* w3    = (const float*)d_in[3];
    const float* w5    = (const float*)d_in[4];
    const float* Wk    = (const float*)d_in[5];
    const float* Wv    = (const float*)d_in[6];
    const float* Wr    = (const float*)d_in[7];
    const float* Wo    = (const float*)d_in[8];
    const float* sd    = (const float*)d_in[9];
    const float* sf    = (const float*)d_in[10];
    float* out = (float*)d_out;

    combine_cw<<<(CC*25 + 255)/256, 256>>>(alpha, w1, w3, w5);
    conv5<<<dim3(CH, CB), CC>>>(x);
    gemm_kvr_h<<<dim3(6, CM/128), 256>>>(Wk, Wv, Wr);

    // scan j = 0: row-major
    wkv_pass1<<<dim3(NCHUNK, CB), CC>>>(sd, 0);
    wkv_cscan<<<CB, CC>>>(sd);
    wkv_pass2<<<dim3(NCHUNK, CB), CC>>>(sd, sf, 0);

    // scan j = 1: column-major
    wkv_pass1<<<dim3(NCHUNK, CB), CC>>>(sd + CC, 1);
    wkv_cscan<<<CB, CC>>>(sd + CC);
    wkv_pass2<<<dim3(NCHUNK, CB), CC>>>(sd + CC, sf + CC, 1);

    gemm_out_h<<<dim3(2, CM/128), 256>>>(Wo, out);
}